// round 1
// baseline (speedup 1.0000x reference)
#include <cuda_runtime.h>
#include <cstdint>

#define N_NODES 50000
#define F_DIM 512
#define C_DIM 64
#define O_DIM 256
#define GRID1 152
#define NT 128
#define NTILES ((N_NODES + NT - 1) / NT)   // 391

typedef unsigned long long ull;

// Scratch (static device arrays; no allocation)
__device__ float g_Mpart[GRID1 * C_DIM * F_DIM];   // per-block partial M = s^T x
__device__ float g_cspart[GRID1 * C_DIM];          // per-block partial colsum(s)
__device__ float g_M[C_DIM * F_DIM];
__device__ float g_cs[C_DIM];
__device__ float g_pooled[C_DIM * F_DIM];

static __device__ __forceinline__ ull pack2(float lo, float hi) {
    ull r; asm("mov.b64 %0, {%1,%2};" : "=l"(r) : "f"(lo), "f"(hi)); return r;
}
static __device__ __forceinline__ void unpack2(ull v, float& lo, float& hi) {
    asm("mov.b64 {%0,%1}, %2;" : "=f"(lo), "=f"(hi) : "l"(v));
}
static __device__ __forceinline__ ull fma2(ull a, ull b, ull c) {
    ull d; asm("fma.rn.f32x2 %0, %1, %2, %3;" : "=l"(d) : "l"(a), "l"(b), "l"(c)); return d;
}

// K1: fused logits -> softmax -> M += s(node) (x) x(node), persistent blocks.
// smem: Wp[512][64] (128KB) + x chunk [32 k4][128 n] float4 swizzled (64KB)
//       + s [128][64] (32KB) + csum[64]
__global__ __launch_bounds__(512, 1) void k1_pool(
    const float* __restrict__ x, const float* __restrict__ Wp, const float* __restrict__ bp)
{
    extern __shared__ float sm[];
    float*  WpS = sm;                                 // 32768 floats
    float4* xs4 = (float4*)(sm + 32768);              // 4096 cells (16B each)
    float4* ss4 = (float4*)(sm + 32768 + 16384);      // 2048 cells
    float*  csS = sm + 32768 + 16384 + 8192;          // 64 floats

    const int tid = threadIdx.x;

    // Stage Wp once (global [512][64] row-major -> same layout in smem)
    {
        const float4* src = (const float4*)Wp;
        float4* dst = (float4*)WpS;
        #pragma unroll
        for (int it = 0; it < 16; ++it) dst[tid + it*512] = src[tid + it*512];
    }
    if (tid < 64) csS[tid] = 0.f;

    const int cq = tid & 15, nq = tid >> 4, n0 = nq * 4;   // logits/softmax ownership
    const int f4 = tid & 31, w  = tid >> 5;                // update ownership (w = warp = c_quad)
    const float4 bp4 = ((const float4*)bp)[cq];

    ull Macc[4][4][2];
    #pragma unroll
    for (int a = 0; a < 4; ++a)
        #pragma unroll
        for (int b = 0; b < 4; ++b) { Macc[a][b][0] = 0ull; Macc[a][b][1] = 0ull; }
    float cs0 = 0.f, cs1 = 0.f, cs2 = 0.f, cs3 = 0.f;

    for (int tile = blockIdx.x; tile < NTILES; tile += GRID1) {
        const int node0 = tile * NT;

        // ---------------- Phase A: logits = x @ Wp + bp ----------------
        ull acc[4][2];
        #pragma unroll
        for (int i = 0; i < 4; ++i) {
            acc[i][0] = pack2(bp4.x, bp4.y);
            acc[i][1] = pack2(bp4.z, bp4.w);
        }

        #pragma unroll
        for (int kc = 0; kc < 4; ++kc) {
            __syncthreads();
            // stage x chunk (transposed + XOR-swizzled): cell[k4][n] = x[node0+n][kc*128 + 4*k4 .. +3]
            #pragma unroll
            for (int it = 0; it < 8; ++it) {
                int j = tid + it * 512;
                int k4 = j & 31, n = j >> 5;
                int node = node0 + n;
                float4 v = make_float4(0.f, 0.f, 0.f, 0.f);
                if (node < N_NODES) v = *(const float4*)(x + (size_t)node * F_DIM + kc * 128 + k4 * 4);
                xs4[k4 * 128 + (n ^ (k4 & 7))] = v;
            }
            __syncthreads();

            #pragma unroll 2
            for (int k4 = 0; k4 < 32; ++k4) {
                float4 xv[4];
                #pragma unroll
                for (int i = 0; i < 4; ++i) xv[i] = xs4[k4 * 128 + ((n0 + i) ^ (k4 & 7))];
                #pragma unroll
                for (int j = 0; j < 4; ++j) {
                    ulonglong2 w2 = *(const ulonglong2*)(WpS + (kc * 128 + k4 * 4 + j) * 64 + cq * 4);
                    #pragma unroll
                    for (int i = 0; i < 4; ++i) {
                        float xj = (j == 0) ? xv[i].x : (j == 1) ? xv[i].y : (j == 2) ? xv[i].z : xv[i].w;
                        ull xx = pack2(xj, xj);
                        acc[i][0] = fma2(w2.x, xx, acc[i][0]);
                        acc[i][1] = fma2(w2.y, xx, acc[i][1]);
                    }
                }
            }
        }

        // ---------------- Phase B: softmax over clusters ----------------
        #pragma unroll
        for (int i = 0; i < 4; ++i) {
            float l0, l1, l2, l3;
            unpack2(acc[i][0], l0, l1);
            unpack2(acc[i][1], l2, l3);
            float m = fmaxf(fmaxf(l0, l1), fmaxf(l2, l3));
            #pragma unroll
            for (int d = 1; d < 16; d <<= 1) m = fmaxf(m, __shfl_xor_sync(0xffffffffu, m, d));
            float e0 = __expf(l0 - m), e1 = __expf(l1 - m), e2 = __expf(l2 - m), e3 = __expf(l3 - m);
            float s = e0 + e1 + e2 + e3;
            #pragma unroll
            for (int d = 1; d < 16; d <<= 1) s += __shfl_xor_sync(0xffffffffu, s, d);
            float r = __frcp_rn(s);
            float4 sv = make_float4(e0 * r, e1 * r, e2 * r, e3 * r);
            if (node0 + n0 + i >= N_NODES) sv = make_float4(0.f, 0.f, 0.f, 0.f);
            cs0 += sv.x; cs1 += sv.y; cs2 += sv.z; cs3 += sv.w;
            ss4[(n0 + i) * 16 + cq] = sv;
        }

        // ---------------- Phase C: M[c][f] += s[n][c] * x[n][f] ----------------
        #pragma unroll
        for (int kc = 0; kc < 4; ++kc) {
            __syncthreads();
            #pragma unroll
            for (int it = 0; it < 8; ++it) {
                int j = tid + it * 512;
                int k4 = j & 31, n = j >> 5;
                int node = node0 + n;
                float4 v = make_float4(0.f, 0.f, 0.f, 0.f);
                if (node < N_NODES) v = *(const float4*)(x + (size_t)node * F_DIM + kc * 128 + k4 * 4);
                xs4[k4 * 128 + (n ^ (k4 & 7))] = v;
            }
            __syncthreads();

            const ulonglong2* xcol = (const ulonglong2*)xs4 + f4 * 128;
            const int sw = f4 & 7;
            #pragma unroll 4
            for (int n = 0; n < 128; ++n) {
                float4 sv = ss4[n * 16 + w];          // broadcast: whole warp same address
                ulonglong2 xv = xcol[n ^ sw];         // conflict-free via swizzle
                ull t0 = pack2(sv.x, sv.x), t1 = pack2(sv.y, sv.y);
                ull t2 = pack2(sv.z, sv.z), t3 = pack2(sv.w, sv.w);
                Macc[kc][0][0] = fma2(xv.x, t0, Macc[kc][0][0]);
                Macc[kc][0][1] = fma2(xv.y, t0, Macc[kc][0][1]);
                Macc[kc][1][0] = fma2(xv.x, t1, Macc[kc][1][0]);
                Macc[kc][1][1] = fma2(xv.y, t1, Macc[kc][1][1]);
                Macc[kc][2][0] = fma2(xv.x, t2, Macc[kc][2][0]);
                Macc[kc][2][1] = fma2(xv.y, t2, Macc[kc][2][1]);
                Macc[kc][3][0] = fma2(xv.x, t3, Macc[kc][3][0]);
                Macc[kc][3][1] = fma2(xv.y, t3, Macc[kc][3][1]);
            }
        }
    }

    // Write per-block partial M
    #pragma unroll
    for (int kc = 0; kc < 4; ++kc)
        #pragma unroll
        for (int cc = 0; cc < 4; ++cc) {
            float a, b, c2, d;
            unpack2(Macc[kc][cc][0], a, b);
            unpack2(Macc[kc][cc][1], c2, d);
            int c = w * 4 + cc;
            int f = kc * 128 + f4 * 4;
            *(float4*)(g_Mpart + (size_t)blockIdx.x * (C_DIM * F_DIM) + c * F_DIM + f) =
                make_float4(a, b, c2, d);
        }

    // Per-block partial colsum(s)
    atomicAdd(&csS[cq * 4 + 0], cs0);
    atomicAdd(&csS[cq * 4 + 1], cs1);
    atomicAdd(&csS[cq * 4 + 2], cs2);
    atomicAdd(&csS[cq * 4 + 3], cs3);
    __syncthreads();
    if (tid < 64) g_cspart[blockIdx.x * 64 + tid] = csS[tid];
}

// K2a: reduce partials
__global__ void k2_reduce() {
    if (blockIdx.x < 128) {
        int idx = blockIdx.x * 256 + threadIdx.x;
        float s = 0.f;
        #pragma unroll 4
        for (int b = 0; b < GRID1; ++b) s += g_Mpart[(size_t)b * (C_DIM * F_DIM) + idx];
        g_M[idx] = s;
    } else if (threadIdx.x < 64) {
        float s = 0.f;
        for (int b = 0; b < GRID1; ++b) s += g_cspart[b * 64 + threadIdx.x];
        g_cs[threadIdx.x] = s;
    }
}

// K2b: pooled = M @ We + colsum(s) (x) be
__global__ void k2_pooled(const float* __restrict__ We, const float* __restrict__ be) {
    int c = blockIdx.x;
    int f = blockIdx.y * 128 + threadIdx.x;
    const float* m = g_M + c * F_DIM;
    float acc = g_cs[c] * be[f];
    #pragma unroll 8
    for (int k = 0; k < F_DIM; ++k) acc += m[k] * We[(size_t)k * F_DIM + f];
    g_pooled[c * F_DIM + f] = acc;
}

// K2c: out = pooled @ Wo + bo
__global__ void k2_out(const float* __restrict__ Wo, const float* __restrict__ bo,
                       float* __restrict__ out) {
    int c = blockIdx.x;
    int o = threadIdx.x;
    const float* p = g_pooled + c * F_DIM;
    float acc = bo[o];
    #pragma unroll 8
    for (int f = 0; f < F_DIM; ++f) acc += p[f] * Wo[(size_t)f * O_DIM + o];
    out[c * O_DIM + o] = acc;
}

extern "C" void kernel_launch(void* const* d_in, const int* in_sizes, int n_in,
                              void* d_out, int out_size) {
    const float* x  = (const float*)d_in[0];
    // d_in[1] = edge_index (int64), d_in[2] = batch (int64): unused by the output
    const float* Wp = (const float*)d_in[3];
    const float* bp = (const float*)d_in[4];
    const float* We = (const float*)d_in[5];
    const float* be = (const float*)d_in[6];
    const float* Wo = (const float*)d_in[7];
    const float* bo = (const float*)d_in[8];
    float* out = (float*)d_out;

    const int SMEM1 = (32768 + 16384 + 8192 + 64) * (int)sizeof(float);  // 229632 B
    cudaFuncSetAttribute(k1_pool, cudaFuncAttributeMaxDynamicSharedMemorySize, SMEM1);

    k1_pool<<<GRID1, 512, SMEM1>>>(x, Wp, bp);
    k2_reduce<<<129, 256>>>();
    k2_pooled<<<dim3(64, 4), 128>>>(We, be);
    k2_out<<<64, 256>>>(Wo, bo, out);
}